// round 1
// baseline (speedup 1.0000x reference)
#include <cuda_runtime.h>
#include <math.h>
#include <stdint.h>

#define P_PTS     16384
#define M_PART    4096
#define HASHMAP_SZ 524288u
#define NUM_LVL   16
#define INV_SQRT2 0.70710678118654752f

// ---------------- scratch (device globals; no allocation allowed) -------------
__device__ __align__(16) float g_xin[232 * P_PTS];
__device__ __align__(16) float g_h0 [256 * P_PTS];
__device__ __align__(16) float g_h1 [256 * P_PTS];
__device__ __align__(16) float g_w0t[232 * 256];
__device__ __align__(16) float g_w1t[256 * 256];
__device__ __align__(16) float g_w2t[256 * 256];
__device__ __align__(16) float g_w3t[256 * 128];
__device__ __align__(16) float g_w4t[256 * 256];
__device__ __align__(16) float g_w5t[256 * 256];
__device__ __align__(16) float g_w6t[256 * 256];
__device__ __align__(16) float g_w7t[256 * 256];
__device__ __align__(16) float g_w8t[256 * 384];

// ---------------- weight transpose + pad:  Wt[k*Npad + n] = W[n*K + k] -------
__global__ void transpose_w(const float* __restrict__ W, float* __restrict__ Wt,
                            int N, int K, int Npad, int total)
{
    int i = blockIdx.x * blockDim.x + threadIdx.x;
    if (i >= total) return;
    int k = i / Npad;
    int n = i - k * Npad;
    Wt[i] = (n < N && k < K) ? W[n * K + k] : 0.0f;
}

// ---------------- feature kernel ---------------------------------------------
// writes x_in column-major: xin[col*P_PTS + p], cols 0..229 (+ zero pad 230,231)
__device__ __forceinline__ void penc3(float* __restrict__ xin, int p, int base,
                                      float a, float b, float c)
{
    xin[(base + 0) * P_PTS + p] = a;
    xin[(base + 1) * P_PTS + p] = b;
    xin[(base + 2) * P_PTS + p] = c;
    float v[3] = {a, b, c};
#pragma unroll
    for (int f = 0; f < 10; ++f) {
        float fr = (float)(1 << f);
#pragma unroll
        for (int ch = 0; ch < 3; ++ch) {
            float s, co;
            sincosf(v[ch] * fr, &s, &co);
            xin[(base + 3 + f * 6 + ch)     * P_PTS + p] = s;
            xin[(base + 3 + f * 6 + 3 + ch) * P_PTS + p] = co;
        }
    }
}

__global__ void feature_kernel(const float* __restrict__ inp,
                               const float* __restrict__ parts,
                               const float* __restrict__ table,
                               float* __restrict__ xin)
{
    __shared__ float sp[M_PART * 3];
    int tid = threadIdx.x;
    for (int i = tid; i < M_PART * 3; i += blockDim.x) sp[i] = parts[i];
    __syncthreads();

    int p = blockIdx.x * blockDim.x + tid;
    float x = inp[3 * p + 0], y = inp[3 * p + 1], z = inp[3 * p + 2];
    float q1 = (x * x + y * y) + z * z;

    // ---- ball query (first 32 by index within radius), single-pass moments ----
    int   cnt  = 0;
    float wsum = 0.f, swx = 0.f, swy = 0.f, swz = 0.f;
    float sdx  = 0.f, sdy = 0.f, sdz = 0.f;
    float s2x  = 0.f, s2y = 0.f, s2z = 0.f;
    const float R2 = 0.01f;
#pragma unroll 4
    for (int j = 0; j < M_PART; ++j) {
        float px = sp[3 * j], py = sp[3 * j + 1], pz = sp[3 * j + 2];
        float qj  = (px * px + py * py) + pz * pz;
        float dot = x * px + y * py + z * pz;
        float d2e = (q1 + qj) - 2.0f * dot;          // mask uses expansion form (like ref)
        if (d2e < R2 && cnt < 32) {
            ++cnt;
            float dx = px - x, dy = py - y, dz = pz - z;
            float d2 = dx * dx + dy * dy + dz * dz;  // w uses direct form (like ref)
            float d  = sqrtf(fmaxf(d2, 1e-24f));
            float dr = d / 0.1f;
            float w  = fmaxf(1.0f - dr * dr * dr, 0.0f);
            wsum += w;
            swx = fmaf(w, px, swx); swy = fmaf(w, py, swy); swz = fmaf(w, pz, swz);
            sdx += dx; sdy += dy; sdz += dz;
            s2x = fmaf(dx, dx, s2x); s2y = fmaf(dy, dy, s2y); s2z = fmaf(dz, dz, s2z);
        }
    }
    // invalid slots: nn = 0 -> diff = -inp, contributes only to wsum
    int ninv = 32 - cnt;
    if (ninv > 0) {
        float d  = sqrtf(fmaxf(q1, 1e-24f));
        float dr = d / 0.1f;
        float w  = fmaxf(1.0f - dr * dr * dr, 0.0f);
        wsum += (float)ninv * w;
    }
    float nf  = (float)cnt;
    float wdn = wsum + 1e-12f;
    float smx = swx / wdn, smy = swy / wdn, smz = swz / wdn;
    float den = nf + 1e-12f;
    float vmx = sdx / den, vmy = sdy / den, vmz = sdz / den;
    float vrx = (s2x - 2.0f * vmx * sdx + nf * vmx * vmx) / den;
    float vry = (s2y - 2.0f * vmy * sdy + nf * vmy * vmy) / den;
    float vrz = (s2z - 2.0f * vmz * sdz + nf * vmz * vmz) / den;

    // ---- positional encodings ----
    penc3(xin, p, 0, x, y, z);               // hit_emb  cols 0..62
    xin[63 * P_PTS + p] = wsum;              // density_emb cols 63..71
#pragma unroll
    for (int f = 0; f < 4; ++f) {
        float s, co;
        sincosf(wsum * (float)(1 << f), &s, &co);
        xin[(64 + 2 * f) * P_PTS + p] = s;
        xin[(65 + 2 * f) * P_PTS + p] = co;
    }
    penc3(xin, p, 72,  smx, smy, smz);       // smoothed_emb cols 72..134
    penc3(xin, p, 135, vrx, vry, vrz);       // var_emb cols 135..197

    // ---- hash encoding, cols 198..229 ----
    float xn[3] = { (x / 1.5f + 1.0f) * 0.5f,
                    (y / 1.5f + 1.0f) * 0.5f,
                    (z / 1.5f + 1.0f) * 0.5f };
#pragma unroll 1
    for (int l = 0; l < NUM_LVL; ++l) {
        double scd   = exp2((7.0 * (double)l) / 15.0) * 16.0 - 1.0;
        float  scale = (float)scd;
        unsigned res = (unsigned)ceil(scd) + 1u;
        bool dense   = ((unsigned long long)res * res * res <= (unsigned long long)HASHMAP_SZ);
        unsigned pg[3]; float fr[3];
#pragma unroll
        for (int c = 0; c < 3; ++c) {
            float pos = fmaf(xn[c], scale, 0.5f);
            float pf  = floorf(pos);
            fr[c] = pos - pf;
            pg[c] = (unsigned)pf;
        }
        float wx[2] = {1.f - fr[0], fr[0]};
        float wy[2] = {1.f - fr[1], fr[1]};
        float wz[2] = {1.f - fr[2], fr[2]};
        const float2* tbl = (const float2*)table + (size_t)l * HASHMAP_SZ;
        float f0 = 0.f, f1 = 0.f;
#pragma unroll
        for (int c = 0; c < 8; ++c) {
            unsigned gx = pg[0] + (unsigned)(c & 1);
            unsigned gy = pg[1] + (unsigned)((c >> 1) & 1);
            unsigned gz = pg[2] + (unsigned)((c >> 2) & 1);
            unsigned idx;
            if (dense) idx = gx + gy * res + gz * res * res;
            else       idx = ((gx * 1u) ^ (gy * 2654435761u) ^ (gz * 805459861u)) & (HASHMAP_SZ - 1u);
            float w = (wx[c & 1] * wy[(c >> 1) & 1]) * wz[(c >> 2) & 1];
            float2 t = tbl[idx];
            f0 = fmaf(w, t.x, f0);
            f1 = fmaf(w, t.y, f1);
        }
        xin[(198 + 2 * l) * P_PTS + p] = f0;
        xin[(199 + 2 * l) * P_PTS + p] = f1;
    }
    xin[230 * P_PTS + p] = 0.0f;   // pad for K=232
    xin[231 * P_PTS + p] = 0.0f;
}

// ---------------- GEMM:  C[m,n] = act( sum_k A[k][m] * Wt[k][n] + b[n] ) -----
// A col-major [K][P_PTS], Wt [K][Npad] (zero padded). BM=BN=128, BK=8, 8x8/thr.
__global__ __launch_bounds__(256, 2)
void mlp_gemm(const float* __restrict__ A,
              const float* __restrict__ Wt,
              const float* __restrict__ bias,
              float* __restrict__ C,
              int Npad, int N, int K, int act, float oscale,
              int row_major, int ldc)
{
    __shared__ float As[8][128];
    __shared__ float Bs[8][128];
    int tid = threadIdx.x;
    int tx = tid & 15, ty = tid >> 4;
    int m0 = blockIdx.y * 128;
    int n0 = blockIdx.x * 128;

    int lk = tid >> 5;            // 0..7
    int lm = (tid & 31) << 2;     // 0..124

    const float* Ap = A  + (size_t)lk * P_PTS + m0 + lm;
    const float* Bp = Wt + (size_t)lk * Npad + n0 + lm;

    float acc[8][8];
#pragma unroll
    for (int i = 0; i < 8; ++i)
#pragma unroll
        for (int j = 0; j < 8; ++j) acc[i][j] = 0.0f;

    float4 apre = *(const float4*)Ap;
    float4 bpre = *(const float4*)Bp;

    int ntiles = K >> 3;
    for (int t = 0; t < ntiles; ++t) {
        *(float4*)&As[lk][lm] = apre;
        *(float4*)&Bs[lk][lm] = bpre;
        __syncthreads();
        if (t + 1 < ntiles) {
            apre = *(const float4*)(Ap + (size_t)(t + 1) * 8 * P_PTS);
            bpre = *(const float4*)(Bp + (size_t)(t + 1) * 8 * Npad);
        }
#pragma unroll
        for (int kk = 0; kk < 8; ++kk) {
            float a[8], b[8];
            *(float4*)&a[0] = *(const float4*)&As[kk][ty * 8];
            *(float4*)&a[4] = *(const float4*)&As[kk][ty * 8 + 4];
            *(float4*)&b[0] = *(const float4*)&Bs[kk][tx * 8];
            *(float4*)&b[4] = *(const float4*)&Bs[kk][tx * 8 + 4];
#pragma unroll
            for (int i = 0; i < 8; ++i)
#pragma unroll
                for (int j = 0; j < 8; ++j)
                    acc[i][j] = fmaf(a[i], b[j], acc[i][j]);
        }
        __syncthreads();
    }

#pragma unroll
    for (int j = 0; j < 8; ++j) {
        int n = n0 + tx * 8 + j;
        if (n >= N) continue;
        float bj = bias[n];
        float out[8];
#pragma unroll
        for (int i = 0; i < 8; ++i) {
            float v = acc[i][j] + bj;
            if (act) {   // softplus(100x)/100 == logaddexp(100x,0)/100
                float yv = 100.0f * v;
                v = (fmaxf(yv, 0.0f) + log1pf(expf(-fabsf(yv)))) * 0.01f;
            }
            out[i] = v * oscale;
        }
        if (row_major) {
#pragma unroll
            for (int i = 0; i < 8; ++i)
                C[(size_t)(m0 + ty * 8 + i) * ldc + n] = out[i];
        } else {
            float4* dst = (float4*)(C + (size_t)n * P_PTS + m0 + ty * 8);
            dst[0] = *(float4*)&out[0];
            dst[1] = *(float4*)&out[4];
        }
    }
}

// ---------------- skip copy: h1 cols 26..255 = x_in * inv_sqrt2 --------------
__global__ void skip_copy_kernel(const float* __restrict__ xin, float* __restrict__ h)
{
    int i = blockIdx.x * blockDim.x + threadIdx.x;
    if (i < (230 * P_PTS) / 4) {
        float4 v = ((const float4*)xin)[i];
        v.x *= INV_SQRT2; v.y *= INV_SQRT2; v.z *= INV_SQRT2; v.w *= INV_SQRT2;
        ((float4*)(h + 26 * P_PTS))[i] = v;
    }
}

// ---------------- launch ------------------------------------------------------
extern "C" void kernel_launch(void* const* d_in, const int* in_sizes, int n_in,
                              void* d_out, int out_size)
{
    const float* inp   = (const float*)d_in[0];
    const float* parts = (const float*)d_in[1];
    const float* table = (const float*)d_in[2];
    const float* W[9];
    const float* B[9];
    for (int l = 0; l < 9; ++l) {
        W[l] = (const float*)d_in[3 + 2 * l];
        B[l] = (const float*)d_in[4 + 2 * l];
    }

    float *xin, *h0, *h1, *wt[9];
    cudaGetSymbolAddress((void**)&xin, g_xin);
    cudaGetSymbolAddress((void**)&h0,  g_h0);
    cudaGetSymbolAddress((void**)&h1,  g_h1);
    cudaGetSymbolAddress((void**)&wt[0], g_w0t);
    cudaGetSymbolAddress((void**)&wt[1], g_w1t);
    cudaGetSymbolAddress((void**)&wt[2], g_w2t);
    cudaGetSymbolAddress((void**)&wt[3], g_w3t);
    cudaGetSymbolAddress((void**)&wt[4], g_w4t);
    cudaGetSymbolAddress((void**)&wt[5], g_w5t);
    cudaGetSymbolAddress((void**)&wt[6], g_w6t);
    cudaGetSymbolAddress((void**)&wt[7], g_w7t);
    cudaGetSymbolAddress((void**)&wt[8], g_w8t);

    const int Kpad[9] = {232,256,256,256,256,256,256,256,256};
    const int Kact[9] = {230,256,256,256,256,256,256,256,256};
    const int Nout[9] = {256,256,256, 26,256,256,256,256,257};
    const int Npad[9] = {256,256,256,128,256,256,256,256,384};

    for (int l = 0; l < 9; ++l) {
        int total = Kpad[l] * Npad[l];
        transpose_w<<<(total + 255) / 256, 256>>>(W[l], wt[l], Nout[l], Kact[l], Npad[l], total);
    }

    feature_kernel<<<128, 128>>>(inp, parts, table, xin);

    auto gemm = [&](const float* Ain, int l, float* Cout, int actf, float os,
                    int rm, int ldc) {
        dim3 grid((Nout[l] + 127) / 128, P_PTS / 128);
        mlp_gemm<<<grid, 256>>>(Ain, wt[l], B[l], Cout, Npad[l], Nout[l], Kpad[l],
                                actf, os, rm, ldc);
    };

    gemm(xin, 0, h0, 1, 1.0f,      0, 0);
    gemm(h0,  1, h1, 1, 1.0f,      0, 0);
    gemm(h1,  2, h0, 1, 1.0f,      0, 0);
    gemm(h0,  3, h1, 1, INV_SQRT2, 0, 0);   // 26 cols of skip input
    skip_copy_kernel<<<((230 * P_PTS / 4) + 255) / 256, 256>>>(xin, h1);
    gemm(h1,  4, h0, 1, 1.0f,      0, 0);
    gemm(h0,  5, h1, 1, 1.0f,      0, 0);
    gemm(h1,  6, h0, 1, 1.0f,      0, 0);
    gemm(h0,  7, h1, 1, 1.0f,      0, 0);
    gemm(h1,  8, (float*)d_out, 0, 1.0f, 1, 257);
}

// round 3
// speedup vs baseline: 1.3202x; 1.3202x over previous
#include <cuda_runtime.h>
#include <cuda_bf16.h>
#include <math.h>
#include <stdint.h>

#define P_PTS     16384
#define M_PART    4096
#define HASHMAP_SZ 524288u
#define NUM_LVL   16
#define INV_SQRT2 0.70710678118654752f

// ---------------- scratch (device globals; no allocation allowed) -------------
// activations: [P][512] bf16  (cols 0..255 = hi, 256..511 = lo)
__device__ __align__(16) float g_xin[232 * P_PTS];
__device__ __align__(16) __nv_bfloat16 g_x[P_PTS * 512];
__device__ __align__(16) __nv_bfloat16 g_a[P_PTS * 512];
__device__ __align__(16) __nv_bfloat16 g_b[P_PTS * 512];
// weights: per-layer [rows][512] bf16, rows: 7x256 + 128 + 384 = 2304
__device__ __align__(16) __nv_bfloat16 g_w[2304 * 512];

// ---------------- PTX helpers -------------------------------------------------
static __device__ __forceinline__ uint32_t smem_u32(const void* p) {
    uint32_t a;
    asm("{ .reg .u64 t; cvta.to.shared.u64 t, %1; cvt.u32.u64 %0, t; }" : "=r"(a) : "l"(p));
    return a;
}
static __device__ __forceinline__ void cp16(uint32_t s, const void* g) {
    asm volatile("cp.async.ca.shared.global [%0], [%1], 16;" :: "r"(s), "l"(g));
}
#define CP_COMMIT()  asm volatile("cp.async.commit_group;" ::: "memory")
#define CP_WAIT1()   asm volatile("cp.async.wait_group 1;" ::: "memory")

static __device__ __forceinline__ void ldsm4(uint32_t& r0, uint32_t& r1,
                                             uint32_t& r2, uint32_t& r3, uint32_t a) {
    asm volatile("ldmatrix.sync.aligned.m8n8.x4.shared.b16 {%0,%1,%2,%3}, [%4];"
                 : "=r"(r0), "=r"(r1), "=r"(r2), "=r"(r3) : "r"(a));
}
static __device__ __forceinline__ void mma16816(float* c, const uint32_t* a,
                                                uint32_t b0, uint32_t b1) {
    asm volatile(
        "mma.sync.aligned.m16n8k16.row.col.f32.bf16.bf16.f32 "
        "{%0,%1,%2,%3}, {%4,%5,%6,%7}, {%8,%9}, {%0,%1,%2,%3};"
        : "+f"(c[0]), "+f"(c[1]), "+f"(c[2]), "+f"(c[3])
        : "r"(a[0]), "r"(a[1]), "r"(a[2]), "r"(a[3]), "r"(b0), "r"(b1));
}

// ---------------- weight prep: fp32 [Nout][Kact] -> bf16 hi/lo [rows][512] ---
__global__ void prep_w(const float* __restrict__ W, __nv_bfloat16* __restrict__ out,
                       int Nout, int Kact, int total)
{
    int i = blockIdx.x * blockDim.x + threadIdx.x;
    if (i >= total) return;
    int n = i >> 8, k = i & 255;
    float v = (n < Nout && k < Kact) ? W[n * Kact + k] : 0.0f;
    __nv_bfloat16 h = __float2bfloat16(v);
    out[(size_t)n * 512 + k]       = h;
    out[(size_t)n * 512 + 256 + k] = __float2bfloat16(v - __bfloat162float(h));
}

// ---------------- transpose + bf16-split: xin col-major -> [P][512] ----------
__global__ void conv_tr(const float* __restrict__ src, __nv_bfloat16* __restrict__ dst,
                        int vlo, int vhi, int srcoff, float scale, int wlo)
{
    __shared__ float s[32][33];
    int tx = threadIdx.x, ty = threadIdx.y;
    int ct = blockIdx.x, pt = blockIdx.y;
#pragma unroll
    for (int r2 = 0; r2 < 4; ++r2) {
        int ci = ty + r2 * 8;
        int c = ct * 32 + ci;
        int p = pt * 32 + tx;
        float v = 0.0f;
        if (c >= vlo && c < vhi) v = src[(size_t)(c + srcoff) * P_PTS + p] * scale;
        s[ci][tx] = v;
    }
    __syncthreads();
#pragma unroll
    for (int r2 = 0; r2 < 4; ++r2) {
        int pi = ty + r2 * 8;
        int p = pt * 32 + pi;
        int c = ct * 32 + tx;
        if (c >= wlo) {
            float v = s[tx][pi];
            __nv_bfloat16 h = __float2bfloat16(v);
            dst[(size_t)p * 512 + c]       = h;
            dst[(size_t)p * 512 + 256 + c] = __float2bfloat16(v - __bfloat162float(h));
        }
    }
}

// ---------------- feature kernel (unchanged, passed in R1) -------------------
__device__ __forceinline__ void penc3(float* __restrict__ xin, int p, int base,
                                      float a, float b, float c)
{
    xin[(base + 0) * P_PTS + p] = a;
    xin[(base + 1) * P_PTS + p] = b;
    xin[(base + 2) * P_PTS + p] = c;
    float v[3] = {a, b, c};
#pragma unroll
    for (int f = 0; f < 10; ++f) {
        float fr = (float)(1 << f);
#pragma unroll
        for (int ch = 0; ch < 3; ++ch) {
            float s, co;
            sincosf(v[ch] * fr, &s, &co);
            xin[(base + 3 + f * 6 + ch)     * P_PTS + p] = s;
            xin[(base + 3 + f * 6 + 3 + ch) * P_PTS + p] = co;
        }
    }
}

__global__ void feature_kernel(const float* __restrict__ inp,
                               const float* __restrict__ parts,
                               const float* __restrict__ table,
                               float* __restrict__ xin)
{
    __shared__ float sp[M_PART * 3];
    int tid = threadIdx.x;
    for (int i = tid; i < M_PART * 3; i += blockDim.x) sp[i] = parts[i];
    __syncthreads();

    int p = blockIdx.x * blockDim.x + tid;
    float x = inp[3 * p + 0], y = inp[3 * p + 1], z = inp[3 * p + 2];
    float q1 = (x * x + y * y) + z * z;

    int   cnt  = 0;
    float wsum = 0.f, swx = 0.f, swy = 0.f, swz = 0.f;
    float sdx  = 0.f, sdy = 0.f, sdz = 0.f;
    float s2x  = 0.f, s2y = 0.f, s2z = 0.f;
    const float R2 = 0.01f;
#pragma unroll 4
    for (int j = 0; j < M_PART; ++j) {
        float px = sp[3 * j], py = sp[3 * j + 1], pz = sp[3 * j + 2];
        float qj  = (px * px + py * py) + pz * pz;
        float dot = x * px + y * py + z * pz;
        float d2e = (q1 + qj) - 2.0f * dot;
        if (d2e < R2 && cnt < 32) {
            ++cnt;
            float dx = px - x, dy = py - y, dz = pz - z;
            float d2 = dx * dx + dy * dy + dz * dz;
            float d  = sqrtf(fmaxf(d2, 1e-24f));
            float dr = d / 0.1f;
            float w  = fmaxf(1.0f - dr * dr * dr, 0.0f);
            wsum += w;
            swx = fmaf(w, px, swx); swy = fmaf(w, py, swy); swz = fmaf(w, pz, swz);
            sdx += dx; sdy += dy; sdz += dz;
            s2x = fmaf(dx, dx, s2x); s2y = fmaf(dy, dy, s2y); s2z = fmaf(dz, dz, s2z);
        }
    }
    int ninv = 32 - cnt;
    if (ninv > 0) {
        float d  = sqrtf(fmaxf(q1, 1e-24f));
        float dr = d / 0.1f;
        float w  = fmaxf(1.0f - dr * dr * dr, 0.0f);
        wsum += (float)ninv * w;
    }
    float nf  = (float)cnt;
    float wdn = wsum + 1e-12f;
    float smx = swx / wdn, smy = swy / wdn, smz = swz / wdn;
    float den = nf + 1e-12f;
    float vmx = sdx / den, vmy = sdy / den, vmz = sdz / den;
    float vrx = (s2x - 2.0f * vmx * sdx + nf * vmx * vmx) / den;
    float vry = (s2y - 2.0f * vmy * sdy + nf * vmy * vmy) / den;
    float vrz = (s2z - 2.0f * vmz * sdz + nf * vmz * vmz) / den;

    penc3(xin, p, 0, x, y, z);
    xin[63 * P_PTS + p] = wsum;
#pragma unroll
    for (int f = 0; f < 4; ++f) {
        float s, co;
        sincosf(wsum * (float)(1 << f), &s, &co);
        xin[(64 + 2 * f) * P_PTS + p] = s;
        xin[(65 + 2 * f) * P_PTS + p] = co;
    }
    penc3(xin, p, 72,  smx, smy, smz);
    penc3(xin, p, 135, vrx, vry, vrz);

    float xn[3] = { (x / 1.5f + 1.0f) * 0.5f,
                    (y / 1.5f + 1.0f) * 0.5f,
                    (z / 1.5f + 1.0f) * 0.5f };
#pragma unroll 1
    for (int l = 0; l < NUM_LVL; ++l) {
        double scd   = exp2((7.0 * (double)l) / 15.0) * 16.0 - 1.0;
        float  scale = (float)scd;
        unsigned res = (unsigned)ceil(scd) + 1u;
        bool dense   = ((unsigned long long)res * res * res <= (unsigned long long)HASHMAP_SZ);
        unsigned pg[3]; float fr[3];
#pragma unroll
        for (int c = 0; c < 3; ++c) {
            float pos = fmaf(xn[c], scale, 0.5f);
            float pf  = floorf(pos);
            fr[c] = pos - pf;
            pg[c] = (unsigned)pf;
        }
        float wx[2] = {1.f - fr[0], fr[0]};
        float wy[2] = {1.f - fr[1], fr[1]};
        float wz[2] = {1.f - fr[2], fr[2]};
        const float2* tbl = (const float2*)table + (size_t)l * HASHMAP_SZ;
        float f0 = 0.f, f1 = 0.f;
#pragma unroll
        for (int c = 0; c < 8; ++c) {
            unsigned gx = pg[0] + (unsigned)(c & 1);
            unsigned gy = pg[1] + (unsigned)((c >> 1) & 1);
            unsigned gz = pg[2] + (unsigned)((c >> 2) & 1);
            unsigned idx;
            if (dense) idx = gx + gy * res + gz * res * res;
            else       idx = ((gx * 1u) ^ (gy * 2654435761u) ^ (gz * 805459861u)) & (HASHMAP_SZ - 1u);
            float w = (wx[c & 1] * wy[(c >> 1) & 1]) * wz[(c >> 2) & 1];
            float2 t = tbl[idx];
            f0 = fmaf(w, t.x, f0);
            f1 = fmaf(w, t.y, f1);
        }
        xin[(198 + 2 * l) * P_PTS + p] = f0;
        xin[(199 + 2 * l) * P_PTS + p] = f1;
    }
    xin[230 * P_PTS + p] = 0.0f;
    xin[231 * P_PTS + p] = 0.0f;
}

// ---------------- bf16x3 GEMM via mma.sync.m16n8k16 ---------------------------
// C[m,n] = act( sum_k A[m,k]*W[n,k] + b[n] )
// A [P][512] hi|lo, W [rows][512] hi|lo. 24 K-tiles of 32:
//   t 0..7  : A hi, W hi     t 8..15 : A lo, W hi     t 16..23: A hi, W lo
#define NKT   24
#define PITCH 40   // bf16 elements per smem row (32 + 8 pad)

__global__ __launch_bounds__(256, 2)
void gemm_mma(const __nv_bfloat16* __restrict__ A, const __nv_bfloat16* __restrict__ W,
              const float* __restrict__ bias,
              __nv_bfloat16* __restrict__ Obf, float* __restrict__ Of32,
              int Nreal, int act, float oscale)
{
    __shared__ __align__(16) __nv_bfloat16 smA[2][128 * PITCH];
    __shared__ __align__(16) __nv_bfloat16 smW[2][128 * PITCH];

    const int tid  = threadIdx.x;
    const int warp = tid >> 5, lane = tid & 31;
    const int m0 = blockIdx.y << 7;
    const int n0 = blockIdx.x << 7;
    const int wm = warp & 3, wn = warp >> 2;

    const uint32_t sA0 = smem_u32(smA);
    const uint32_t sW0 = smem_u32(smW);

    // loader: thread covers 2x 16B chunks of A tile and 2x of W tile
    const int q0 = tid * 2;
    const int lr0 = q0 >> 2,      lc0 = (q0 & 3) << 3;        // row, col(elem)
    const int lr1 = (q0 + 1) >> 2, lc1 = ((q0 + 1) & 3) << 3;

    auto load_tile = [&](int t, int s) {
        int chunk = t >> 3, koff = (t & 7) << 5;
        int acol = ((chunk == 1) ? 256 : 0) + koff;
        int wcol = ((chunk == 2) ? 256 : 0) + koff;
        uint32_t sa = sA0 + s * (128 * PITCH * 2);
        uint32_t sw = sW0 + s * (128 * PITCH * 2);
        cp16(sa + (lr0 * PITCH + lc0) * 2, A + (size_t)(m0 + lr0) * 512 + acol + lc0);
        cp16(sa + (lr1 * PITCH + lc1) * 2, A + (size_t)(m0 + lr1) * 512 + acol + lc1);
        cp16(sw + (lr0 * PITCH + lc0) * 2, W + (size_t)(n0 + lr0) * 512 + wcol + lc0);
        cp16(sw + (lr1 * PITCH + lc1) * 2, W + (size_t)(n0 + lr1) * 512 + wcol + lc1);
    };

    float c[2][8][4];
#pragma unroll
    for (int mi = 0; mi < 2; ++mi)
#pragma unroll
        for (int nf = 0; nf < 8; ++nf)
#pragma unroll
            for (int r = 0; r < 4; ++r) c[mi][nf][r] = 0.0f;

    load_tile(0, 0);
    CP_COMMIT();

    const int arow = (lane & 15);
    const int acol8 = (lane >> 4) << 3;

    for (int t = 0; t < NKT; ++t) {
        if (t + 1 < NKT) load_tile(t + 1, (t + 1) & 1);
        CP_COMMIT();
        CP_WAIT1();
        __syncthreads();

        uint32_t sa = sA0 + (t & 1) * (128 * PITCH * 2);
        uint32_t sw = sW0 + (t & 1) * (128 * PITCH * 2);
#pragma unroll
        for (int ks = 0; ks < 2; ++ks) {
            uint32_t a[2][4];
#pragma unroll
            for (int mi = 0; mi < 2; ++mi) {
                uint32_t addr = sa + ((wm * 32 + mi * 16 + arow) * PITCH + ks * 16 + acol8) * 2;
                ldsm4(a[mi][0], a[mi][1], a[mi][2], a[mi][3], addr);
            }
            uint32_t b[4][4];
#pragma unroll
            for (int nb = 0; nb < 4; ++nb) {
                uint32_t addr = sw + ((wn * 64 + nb * 16 + arow) * PITCH + ks * 16 + acol8) * 2;
                ldsm4(b[nb][0], b[nb][1], b[nb][2], b[nb][3], addr);
            }
#pragma unroll
            for (int mi = 0; mi < 2; ++mi)
#pragma unroll
                for (int nb = 0; nb < 4; ++nb) {
                    mma16816(c[mi][nb * 2],     a[mi], b[nb][0], b[nb][2]);
                    mma16816(c[mi][nb * 2 + 1], a[mi], b[nb][1], b[nb][3]);
                }
        }
        __syncthreads();
    }

    // ---- epilogue: bias + softplus + store --------------------------------
#pragma unroll
    for (int mi = 0; mi < 2; ++mi) {
        int mbase = m0 + wm * 32 + mi * 16 + (lane >> 2);
#pragma unroll
        for (int nf = 0; nf < 8; ++nf) {
            int n = n0 + wn * 64 + nf * 8 + ((lane & 3) << 1);
            if (n >= Nreal && n + 1 >= Nreal) continue;
            float b0 = (n < Nreal)     ? __ldg(bias + n)     : 0.0f;
            float b1 = (n + 1 < Nreal) ? __ldg(bias + n + 1) : 0.0f;
#pragma unroll
            for (int r2 = 0; r2 < 2; ++r2) {
                int m = mbase + r2 * 8;
                float v0 = c[mi][nf][r2 * 2 + 0] + b0;
                float v1 = c[mi][nf][r2 * 2 + 1] + b1;
                if (act) {
                    float y0 = 100.0f * v0, y1 = 100.0f * v1;
                    v0 = (fmaxf(y0, 0.0f) + log1pf(expf(-fabsf(y0)))) * 0.01f;
                    v1 = (fmaxf(y1, 0.0f) + log1pf(expf(-fabsf(y1)))) * 0.01f;
                }
                v0 *= oscale; v1 *= oscale;
                if (Of32) {
                    if (n < Nreal)     Of32[(size_t)m * 257 + n]     = v0;
                    if (n + 1 < Nreal) Of32[(size_t)m * 257 + n + 1] = v1;
                } else {
                    // Nreal even here; pair is valid iff n < Nreal
                    __nv_bfloat16 h0 = __float2bfloat16(v0);
                    __nv_bfloat16 h1 = __float2bfloat16(v1);
                    __nv_bfloat16 l0 = __float2bfloat16(v0 - __bfloat162float(h0));
                    __nv_bfloat16 l1 = __float2bfloat16(v1 - __bfloat162float(h1));
                    uint32_t hw = (uint32_t)__bfloat16_as_ushort(h0) |
                                  ((uint32_t)__bfloat16_as_ushort(h1) << 16);
                    uint32_t lw = (uint32_t)__bfloat16_as_ushort(l0) |
                                  ((uint32_t)__bfloat16_as_ushort(l1) << 16);
                    *(uint32_t*)(Obf + (size_t)m * 512 + n)       = hw;
                    *(uint32_t*)(Obf + (size_t)m * 512 + 256 + n) = lw;
                }
            }
        }
    }
}

// ---------------- launch ------------------------------------------------------
extern "C" void kernel_launch(void* const* d_in, const int* in_sizes, int n_in,
                              void* d_out, int out_size)
{
    const float* inp   = (const float*)d_in[0];
    const float* parts = (const float*)d_in[1];
    const float* table = (const float*)d_in[2];
    const float* W[9];
    const float* B[9];
    for (int l = 0; l < 9; ++l) {
        W[l] = (const float*)d_in[3 + 2 * l];
        B[l] = (const float*)d_in[4 + 2 * l];
    }

    float* xin;
    __nv_bfloat16 *xb, *ab, *bb, *wbase;
    cudaGetSymbolAddress((void**)&xin, g_xin);
    cudaGetSymbolAddress((void**)&xb, g_x);
    cudaGetSymbolAddress((void**)&ab, g_a);
    cudaGetSymbolAddress((void**)&bb, g_b);
    cudaGetSymbolAddress((void**)&wbase, g_w);

    static const int Nout[9]  = {256, 256, 256, 26, 256, 256, 256, 256, 257};
    static const int Kact[9]  = {230, 256, 256, 256, 256, 256, 256, 256, 256};
    static const int Nrows[9] = {256, 256, 256, 128, 256, 256, 256, 256, 384};

    __nv_bfloat16* wt[9];
    {
        size_t off = 0;
        for (int l = 0; l < 9; ++l) { wt[l] = wbase + off; off += (size_t)Nrows[l] * 512; }
    }

    for (int l = 0; l < 9; ++l) {
        int total = Nrows[l] * 256;
        prep_w<<<(total + 255) / 256, 256>>>(W[l], wt[l], Nout[l], Kact[l], total);
    }

    feature_kernel<<<128, 128>>>(inp, parts, table, xin);
    // L0 input: cols 0..231 from xin (cols 232..255 zeroed)
    conv_tr<<<dim3(8, P_PTS / 32), dim3(32, 8)>>>(xin, xb, 0, 232, 0, 1.0f, 0);

    auto gemm = [&](const __nv_bfloat16* Ain, int l, __nv_bfloat16* Obf, float* Of,
                    int act, float os) {
        dim3 grid(Nrows[l] / 128, P_PTS / 128);
        gemm_mma<<<grid, 256>>>(Ain, wt[l], B[l], Obf, Of, Nout[l], act, os);
    };

    gemm(xb, 0, ab, nullptr, 1, 1.0f);
    gemm(ab, 1, bb, nullptr, 1, 1.0f);
    gemm(bb, 2, ab, nullptr, 1, 1.0f);
    gemm(ab, 3, bb, nullptr, 1, INV_SQRT2);   // writes cols 0..25 (pre-scaled)
    // skip: cols 26..255 = xin * inv_sqrt2
    conv_tr<<<dim3(8, P_PTS / 32), dim3(32, 8)>>>(xin, bb, 26, 256, -26, INV_SQRT2, 26);
    gemm(bb, 4, ab, nullptr, 1, 1.0f);
    gemm(ab, 5, bb, nullptr, 1, 1.0f);
    gemm(bb, 6, ab, nullptr, 1, 1.0f);
    gemm(ab, 7, bb, nullptr, 1, 1.0f);
    gemm(bb, 8, nullptr, (float*)d_out, 0, 1.0f);
}